// round 2
// baseline (speedup 1.0000x reference)
#include <cuda_runtime.h>
#include <math.h>

#define N_NODES 20000
#define N_EDGES 320000
#define TOT_EDGES (N_EDGES + N_NODES)
#define HID 64
#define NH 4
#define HC 64
#define FDIM 256  // NH*HC

// ---------------- scratch (static device allocations, allowed) ----------------
__device__ float g_hA[N_NODES * HID];
__device__ float g_hB[N_NODES * HID];
__device__ float g_hproj[N_NODES * FDIM];
__device__ float g_asrc[N_NODES * NH];
__device__ float g_adst[N_NODES * NH];
__device__ int   g_deg[N_NODES];
__device__ int   g_off[N_NODES + 1];
__device__ int   g_cursor[N_NODES];
__device__ int   g_srcs[TOT_EDGES];
__device__ int   g_is64;

__device__ __forceinline__ float eluf(float x) {
    return x > 0.f ? x : (__expf(x) - 1.f);
}
__device__ __forceinline__ float lrelu(float x) {
    return x > 0.f ? x : 0.2f * x;
}

// ---------------- edge-index width detection (int32 vs int64) ----------------
__global__ void k_detect(const int* ei_words) {
    __shared__ int any;
    if (threadIdx.x == 0) any = 0;
    __syncthreads();
    int found = 0;
    // if data is int64 (values < 2^31, non-negative), every odd 32-bit word is 0.
    for (int i = 1 + 2 * threadIdx.x; i < 2048; i += 2 * blockDim.x)
        if (ei_words[i] != 0) found = 1;
    if (found) atomicOr(&any, 1);
    __syncthreads();
    if (threadIdx.x == 0) g_is64 = any ? 0 : 1;
}

__device__ __forceinline__ int edge_val(const void* ei, long long idx) {
    if (g_is64) return (int)((const long long*)ei)[idx];
    return ((const int*)ei)[idx];
}

// ---------------- CSR build ----------------
__global__ void k_deg_init() {
    int i = blockIdx.x * blockDim.x + threadIdx.x;
    if (i < N_NODES) g_deg[i] = 1;  // self loop
}

__global__ void k_count(const void* ei) {
    int e = blockIdx.x * blockDim.x + threadIdx.x;
    if (e >= N_EDGES) return;
    int d = edge_val(ei, (long long)N_EDGES + e);
    atomicAdd(&g_deg[d], 1);
}

__global__ void k_scan() {  // single block, 1024 threads
    __shared__ int ssum[1024];
    const int CH = (N_NODES + 1023) / 1024;  // 20
    int t = threadIdx.x;
    int base = t * CH;
    int s = 0;
    for (int i = 0; i < CH; i++) {
        int idx = base + i;
        if (idx < N_NODES) s += g_deg[idx];
    }
    ssum[t] = s;
    __syncthreads();
    for (int o = 1; o < 1024; o <<= 1) {
        int v = (t >= o) ? ssum[t - o] : 0;
        __syncthreads();
        ssum[t] += v;
        __syncthreads();
    }
    int run = ssum[t] - s;  // exclusive prefix of this chunk
    for (int i = 0; i < CH; i++) {
        int idx = base + i;
        if (idx < N_NODES) {
            g_off[idx] = run;
            g_cursor[idx] = run;
            run += g_deg[idx];
        }
    }
    if (t == 1023) g_off[N_NODES] = ssum[1023];
}

__global__ void k_scatter(const void* ei) {
    int e = blockIdx.x * blockDim.x + threadIdx.x;
    if (e >= TOT_EDGES) return;
    int s, d;
    if (e < N_EDGES) {
        s = edge_val(ei, e);
        d = edge_val(ei, (long long)N_EDGES + e);
    } else {
        s = d = e - N_EDGES;  // self loop
    }
    int p = atomicAdd(&g_cursor[d], 1);
    g_srcs[p] = s;
}

// ---------------- encoder MLP: 8 -> 32 (elu) -> 64 (elu) ----------------
__global__ void k_encoder(const float* __restrict__ x,
                          const float* __restrict__ W1, const float* __restrict__ b1,
                          const float* __restrict__ W2, const float* __restrict__ b2) {
    __shared__ float sW1[8 * 32], sb1[32], sW2[32 * 64], sb2[64];
    for (int i = threadIdx.x; i < 8 * 32; i += blockDim.x) sW1[i] = W1[i];
    for (int i = threadIdx.x; i < 32; i += blockDim.x) sb1[i] = b1[i];
    for (int i = threadIdx.x; i < 32 * 64; i += blockDim.x) sW2[i] = W2[i];
    for (int i = threadIdx.x; i < 64; i += blockDim.x) sb2[i] = b2[i];
    __syncthreads();
    int n = blockIdx.x * blockDim.x + threadIdx.x;
    if (n >= N_NODES) return;
    float xi[8];
#pragma unroll
    for (int i = 0; i < 8; i++) xi[i] = x[n * 8 + i];
    float hid[32];
#pragma unroll
    for (int j = 0; j < 32; j++) {
        float a = sb1[j];
#pragma unroll
        for (int i = 0; i < 8; i++) a += xi[i] * sW1[i * 32 + j];
        hid[j] = eluf(a);
    }
    for (int j = 0; j < 64; j++) {
        float a = sb2[j];
#pragma unroll
        for (int i = 0; i < 32; i++) a += hid[i] * sW2[i * 64 + j];
        g_hA[n * 64 + j] = eluf(a);
    }
}

// ---------------- GAT projection GEMM: [N,64] @ [64,256] ----------------
// tile: 32 rows x 128 cols per block; grid (ceil(N/32), 2)
__global__ void k_gemm(const float* __restrict__ hin, const float* __restrict__ W) {
    __shared__ float sW[64 * 128];  // 32KB
    __shared__ float sx[32 * 64];   // 8KB
    int colbase = blockIdx.y * 128;
    for (int i = threadIdx.x; i < 64 * 128; i += blockDim.x) {
        int k = i / 128, c = i % 128;
        sW[i] = W[k * 256 + colbase + c];
    }
    int row0 = blockIdx.x * 32;
    for (int i = threadIdx.x; i < 32 * 64; i += blockDim.x) {
        int r = i / 64, c = i % 64;
        int n = row0 + r;
        sx[i] = (n < N_NODES) ? hin[n * 64 + c] : 0.f;
    }
    __syncthreads();
    int t = threadIdx.x;
    int c = t & 127;
    int rbase = (t >> 7) * 16;  // 0 or 16
    float acc[16];
#pragma unroll
    for (int r = 0; r < 16; r++) acc[r] = 0.f;
    for (int k = 0; k < 64; k++) {
        float w = sW[k * 128 + c];
#pragma unroll
        for (int r = 0; r < 16; r++) acc[r] += sx[(rbase + r) * 64 + k] * w;
    }
#pragma unroll
    for (int r = 0; r < 16; r++) {
        int n = row0 + rbase + r;
        if (n < N_NODES) g_hproj[(long long)n * 256 + colbase + c] = acc[r];
    }
}

// ---------------- attention coefficients: a_src/a_dst per (node, head) ----------------
__global__ void k_att(const float* __restrict__ as, const float* __restrict__ ad) {
    int warp = (blockIdx.x * blockDim.x + threadIdx.x) >> 5;
    int lane = threadIdx.x & 31;
    if (warp >= N_NODES) return;
    const float4* hp = (const float4*)(g_hproj + (long long)warp * 256);
    float4 h0 = hp[lane * 2], h1 = hp[lane * 2 + 1];
    int head = lane >> 3;
    int off = head * 64 + (lane & 7) * 8;
    const float4* ap = (const float4*)(as + off);
    float4 a0 = ap[0], a1 = ap[1];
    const float4* dp = (const float4*)(ad + off);
    float4 d0 = dp[0], d1 = dp[1];
    float ps = h0.x * a0.x + h0.y * a0.y + h0.z * a0.z + h0.w * a0.w +
               h1.x * a1.x + h1.y * a1.y + h1.z * a1.z + h1.w * a1.w;
    float pd = h0.x * d0.x + h0.y * d0.y + h0.z * d0.z + h0.w * d0.w +
               h1.x * d1.x + h1.y * d1.y + h1.z * d1.z + h1.w * d1.w;
#pragma unroll
    for (int o = 4; o >= 1; o >>= 1) {
        ps += __shfl_down_sync(0xffffffffu, ps, o);
        pd += __shfl_down_sync(0xffffffffu, pd, o);
    }
    if ((lane & 7) == 0) {
        g_asrc[warp * 4 + head] = ps;
        g_adst[warp * 4 + head] = pd;
    }
}

// ---------------- aggregation: warp per dst node ----------------
__global__ void k_agg(const float* __restrict__ bias,
                      const float* __restrict__ hin, float* __restrict__ hout) {
    __shared__ int   s_src[8][32];
    __shared__ float s_e[8][32][4];
    int wib = threadIdx.x >> 5;
    int lane = threadIdx.x & 31;
    int d = blockIdx.x * 8 + wib;
    if (d >= N_NODES) return;
    int start = g_off[d], end = g_off[d + 1];
    float4 adst = *(const float4*)(g_adst + d * 4);

    // pass 1: segment max per head
    float m0 = -1e30f, m1 = -1e30f, m2 = -1e30f, m3 = -1e30f;
    for (int i = start + lane; i < end; i += 32) {
        int s = g_srcs[i];
        float4 a = *(const float4*)(g_asrc + s * 4);
        m0 = fmaxf(m0, lrelu(a.x + adst.x));
        m1 = fmaxf(m1, lrelu(a.y + adst.y));
        m2 = fmaxf(m2, lrelu(a.z + adst.z));
        m3 = fmaxf(m3, lrelu(a.w + adst.w));
    }
#pragma unroll
    for (int o = 16; o; o >>= 1) {
        m0 = fmaxf(m0, __shfl_xor_sync(0xffffffffu, m0, o));
        m1 = fmaxf(m1, __shfl_xor_sync(0xffffffffu, m1, o));
        m2 = fmaxf(m2, __shfl_xor_sync(0xffffffffu, m2, o));
        m3 = fmaxf(m3, __shfl_xor_sync(0xffffffffu, m3, o));
    }

    int head = lane >> 3;
    float acc[8];
#pragma unroll
    for (int j = 0; j < 8; j++) acc[j] = 0.f;
    float den0 = 0.f, den1 = 0.f, den2 = 0.f, den3 = 0.f;

    for (int base = start; base < end; base += 32) {
        int i = base + lane;
        int cnt = min(32, end - base);
        if (i < end) {
            int s = g_srcs[i];
            float4 a = *(const float4*)(g_asrc + s * 4);
            float e0 = __expf(lrelu(a.x + adst.x) - m0);
            float e1 = __expf(lrelu(a.y + adst.y) - m1);
            float e2 = __expf(lrelu(a.z + adst.z) - m2);
            float e3 = __expf(lrelu(a.w + adst.w) - m3);
            den0 += e0; den1 += e1; den2 += e2; den3 += e3;
            s_src[wib][lane] = s;
            s_e[wib][lane][0] = e0;
            s_e[wib][lane][1] = e1;
            s_e[wib][lane][2] = e2;
            s_e[wib][lane][3] = e3;
        }
        __syncwarp();
        for (int k = 0; k < cnt; k++) {
            int s = s_src[wib][k];
            float eh = s_e[wib][k][head];
            const float4* hp = (const float4*)(g_hproj + (long long)s * 256 + lane * 8);
            float4 p0 = hp[0], p1 = hp[1];
            acc[0] += eh * p0.x; acc[1] += eh * p0.y;
            acc[2] += eh * p0.z; acc[3] += eh * p0.w;
            acc[4] += eh * p1.x; acc[5] += eh * p1.y;
            acc[6] += eh * p1.z; acc[7] += eh * p1.w;
        }
        __syncwarp();
    }

#pragma unroll
    for (int o = 16; o; o >>= 1) {
        den0 += __shfl_xor_sync(0xffffffffu, den0, o);
        den1 += __shfl_xor_sync(0xffffffffu, den1, o);
        den2 += __shfl_xor_sync(0xffffffffu, den2, o);
        den3 += __shfl_xor_sync(0xffffffffu, den3, o);
    }
    float dh = (head == 0) ? den0 : (head == 1) ? den1 : (head == 2) ? den2 : den3;
    float inv = 1.f / (dh + 1e-16f);
#pragma unroll
    for (int j = 0; j < 8; j++) acc[j] *= inv;

    // mean over heads: sum lanes {L, L^8, L^16, L^24}
#pragma unroll
    for (int j = 0; j < 8; j++) {
        acc[j] += __shfl_xor_sync(0xffffffffu, acc[j], 8);
        acc[j] += __shfl_xor_sync(0xffffffffu, acc[j], 16);
    }
    if (lane < 8) {
#pragma unroll
        for (int j = 0; j < 8; j++) {
            int cc = lane * 8 + j;
            hout[d * 64 + cc] = 0.25f * acc[j] + bias[cc] + hin[d * 64 + cc];
        }
    }
}

// ---------------- output MLP: 64 -> 64 (elu) -> 32 (elu) -> 8 ----------------
__global__ void k_outmlp(const float* __restrict__ hin,
                         const float* __restrict__ W1, const float* __restrict__ b1,
                         const float* __restrict__ W2, const float* __restrict__ b2,
                         const float* __restrict__ W3, const float* __restrict__ b3,
                         float* __restrict__ out) {
    __shared__ float sW1[64 * 64], sW2[64 * 32], sW3[32 * 8];
    __shared__ float sb1[64], sb2[32], sb3[8];
    __shared__ float sh[8][64], sh1[8][64], sh2[8][32];
    for (int i = threadIdx.x; i < 64 * 64; i += blockDim.x) sW1[i] = W1[i];
    for (int i = threadIdx.x; i < 64 * 32; i += blockDim.x) sW2[i] = W2[i];
    for (int i = threadIdx.x; i < 32 * 8; i += blockDim.x) sW3[i] = W3[i];
    for (int i = threadIdx.x; i < 64; i += blockDim.x) sb1[i] = b1[i];
    for (int i = threadIdx.x; i < 32; i += blockDim.x) sb2[i] = b2[i];
    for (int i = threadIdx.x; i < 8; i += blockDim.x) sb3[i] = b3[i];
    __syncthreads();
    int wib = threadIdx.x >> 5;
    int lane = threadIdx.x & 31;
    int d = blockIdx.x * 8 + wib;
    if (d >= N_NODES) return;
    sh[wib][lane] = hin[d * 64 + lane];
    sh[wib][lane + 32] = hin[d * 64 + lane + 32];
    __syncwarp();
    float a0 = sb1[lane], a1 = sb1[lane + 32];
#pragma unroll
    for (int i = 0; i < 64; i++) {
        float xv = sh[wib][i];
        a0 += xv * sW1[i * 64 + lane];
        a1 += xv * sW1[i * 64 + lane + 32];
    }
    sh1[wib][lane] = eluf(a0);
    sh1[wib][lane + 32] = eluf(a1);
    __syncwarp();
    float a = sb2[lane];
#pragma unroll
    for (int i = 0; i < 64; i++) a += sh1[wib][i] * sW2[i * 32 + lane];
    sh2[wib][lane] = eluf(a);
    __syncwarp();
    if (lane < 8) {
        float o = sb3[lane];
#pragma unroll
        for (int i = 0; i < 32; i++) o += sh2[wib][i] * sW3[i * 8 + lane];
        out[d * 8 + lane] = o;
    }
}

// ---------------- launch ----------------
extern "C" void kernel_launch(void* const* d_in, const int* in_sizes, int n_in,
                              void* d_out, int out_size) {
    const float* x      = (const float*)d_in[0];
    const void*  ei     = d_in[1];
    const float* W_enc1 = (const float*)d_in[2];
    const float* b_enc1 = (const float*)d_in[3];
    const float* W_enc2 = (const float*)d_in[4];
    const float* b_enc2 = (const float*)d_in[5];
    const float* W_g[3]  = {(const float*)d_in[6],  (const float*)d_in[10], (const float*)d_in[14]};
    const float* as_[3]  = {(const float*)d_in[7],  (const float*)d_in[11], (const float*)d_in[15]};
    const float* ad_[3]  = {(const float*)d_in[8],  (const float*)d_in[12], (const float*)d_in[16]};
    const float* bg_[3]  = {(const float*)d_in[9],  (const float*)d_in[13], (const float*)d_in[17]};
    const float* W_o1 = (const float*)d_in[18];
    const float* b_o1 = (const float*)d_in[19];
    const float* W_o2 = (const float*)d_in[20];
    const float* b_o2 = (const float*)d_in[21];
    const float* W_o3 = (const float*)d_in[22];
    const float* b_o3 = (const float*)d_in[23];
    float* out = (float*)d_out;

    // edge dtype detection + CSR build
    k_detect<<<1, 256>>>((const int*)ei);
    k_deg_init<<<(N_NODES + 255) / 256, 256>>>();
    k_count<<<(N_EDGES + 255) / 256, 256>>>(ei);
    k_scan<<<1, 1024>>>();
    k_scatter<<<(TOT_EDGES + 255) / 256, 256>>>(ei);

    // encoder
    k_encoder<<<(N_NODES + 255) / 256, 256>>>(x, W_enc1, b_enc1, W_enc2, b_enc2);

    float* bufs[4] = {nullptr, nullptr, nullptr, nullptr};
    // resolve device symbol addresses on host once per call (cheap, not a stream op)
    static float* hA_p = nullptr;
    static float* hB_p = nullptr;
    if (!hA_p) {
        cudaGetSymbolAddress((void**)&hA_p, g_hA);
        cudaGetSymbolAddress((void**)&hB_p, g_hB);
    }
    (void)bufs;

    dim3 ggrid((N_NODES + 31) / 32, 2);

    // layer 1: hA -> hB
    k_gemm<<<ggrid, 256>>>(hA_p, W_g[0]);
    k_att<<<(N_NODES * 32 + 255) / 256, 256>>>(as_[0], ad_[0]);
    k_agg<<<(N_NODES + 7) / 8, 256>>>(bg_[0], hA_p, hB_p);
    // layer 2: hB -> hA
    k_gemm<<<ggrid, 256>>>(hB_p, W_g[1]);
    k_att<<<(N_NODES * 32 + 255) / 256, 256>>>(as_[1], ad_[1]);
    k_agg<<<(N_NODES + 7) / 8, 256>>>(bg_[1], hB_p, hA_p);
    // layer 3: hA -> hB
    k_gemm<<<ggrid, 256>>>(hA_p, W_g[2]);
    k_att<<<(N_NODES * 32 + 255) / 256, 256>>>(as_[2], ad_[2]);
    k_agg<<<(N_NODES + 7) / 8, 256>>>(bg_[2], hA_p, hB_p);

    // output MLP
    k_outmlp<<<(N_NODES + 7) / 8, 256>>>(hB_p, W_o1, b_o1, W_o2, b_o2, W_o3, b_o3, out);

    (void)in_sizes; (void)n_in; (void)out_size;
}

// round 5
// speedup vs baseline: 1.2152x; 1.2152x over previous
#include <cuda_runtime.h>
#include <cuda_fp16.h>
#include <math.h>

#define N_NODES 20000
#define N_EDGES 320000
#define TOT_EDGES (N_EDGES + N_NODES)
#define HID 64
#define NH 4
#define FDIM 256
#define NB_SCAN 79  // ceil(20000/256)

// ---------------- scratch ----------------
__device__ float  g_hA[N_NODES * HID];
__device__ float  g_hB[N_NODES * HID];
__device__ __half g_hproj[N_NODES * FDIM];
__device__ float  g_asrc[N_NODES * NH];
__device__ float  g_adst[N_NODES * NH];
__device__ int    g_deg[N_NODES];
__device__ int    g_off[N_NODES + 1];
__device__ int    g_cursor[N_NODES];
__device__ int    g_srcs[TOT_EDGES];
__device__ int    g_bsum[NB_SCAN];
__device__ int    g_bbase[128];
__device__ int    g_is64;

__device__ __forceinline__ float eluf(float x) { return x > 0.f ? x : (__expf(x) - 1.f); }
__device__ __forceinline__ float lrelu(float x) { return x > 0.f ? x : 0.2f * x; }

__device__ __forceinline__ unsigned long long pack2(float a, float b) {
    unsigned long long r;
    asm("mov.b64 %0,{%1,%2};" : "=l"(r) : "f"(a), "f"(b));
    return r;
}
__device__ __forceinline__ float2 unpk2(unsigned long long v) {
    float2 r;
    asm("mov.b64 {%0,%1},%2;" : "=f"(r.x), "=f"(r.y) : "l"(v));
    return r;
}
__device__ __forceinline__ void fma2(unsigned long long& d, unsigned long long a, unsigned long long b) {
    asm("fma.rn.f32x2 %0,%1,%2,%0;" : "+l"(d) : "l"(a), "l"(b));
}

// ---------------- init: deg=1 + edge dtype detect ----------------
__global__ void k_init(const int* ei_words) {
    int i = blockIdx.x * blockDim.x + threadIdx.x;
    if (i < N_NODES) g_deg[i] = 1;
    if (blockIdx.x == 0) {
        __shared__ int any;
        if (threadIdx.x == 0) any = 0;
        __syncthreads();
        int found = 0;
        for (int j = 1 + 2 * threadIdx.x; j < 2048; j += 2 * blockDim.x)
            if (ei_words[j] != 0) found = 1;
        if (found) atomicOr(&any, 1);
        __syncthreads();
        if (threadIdx.x == 0) g_is64 = any ? 0 : 1;
    }
}

__device__ __forceinline__ int edge_val(const void* ei, long long idx) {
    if (g_is64) return (int)((const long long*)ei)[idx];
    return ((const int*)ei)[idx];
}

__global__ void k_count(const void* ei) {
    int e = blockIdx.x * blockDim.x + threadIdx.x;
    if (e >= N_EDGES) return;
    int d = edge_val(ei, (long long)N_EDGES + e);
    atomicAdd(&g_deg[d], 1);
}

// ---------------- hierarchical scan ----------------
__global__ void k_scan1() {
    int t = threadIdx.x;
    int i = blockIdx.x * 256 + t;
    int v = (i < N_NODES) ? g_deg[i] : 0;
    int lane = t & 31, w = t >> 5;
    int s = v;
#pragma unroll
    for (int o = 1; o < 32; o <<= 1) {
        int u = __shfl_up_sync(0xffffffffu, s, o);
        if (lane >= o) s += u;
    }
    __shared__ int wsum[8];
    if (lane == 31) wsum[w] = s;
    __syncthreads();
    if (w == 0 && lane < 8) {
        int x = wsum[lane];
#pragma unroll
        for (int o = 1; o < 8; o <<= 1) {
            int u = __shfl_up_sync(0xffu, x, o);
            if (lane >= o) x += u;
        }
        wsum[lane] = x;
    }
    __syncthreads();
    int base = (w > 0) ? wsum[w - 1] : 0;
    if (i < N_NODES) g_off[i] = base + s - v;  // block-local exclusive
    if (t == 0) g_bsum[blockIdx.x] = wsum[7];
}

__global__ void k_scan2() {
    __shared__ int sh[128];
    int t = threadIdx.x;
    int v = (t < NB_SCAN) ? g_bsum[t] : 0;
    sh[t] = v;
    __syncthreads();
    for (int o = 1; o < 128; o <<= 1) {
        int u = (t >= o) ? sh[t - o] : 0;
        __syncthreads();
        sh[t] += u;
        __syncthreads();
    }
    g_bbase[t] = sh[t] - v;  // exclusive
}

__global__ void k_scan3() {
    int i = blockIdx.x * 256 + threadIdx.x;
    if (i < N_NODES) {
        int off = g_off[i] + g_bbase[blockIdx.x];
        g_off[i] = off;
        g_cursor[i] = off;
    }
    if (i == 0) g_off[N_NODES] = TOT_EDGES;
}

__global__ void k_scatter(const void* ei) {
    int e = blockIdx.x * blockDim.x + threadIdx.x;
    if (e >= TOT_EDGES) return;
    int s, d;
    if (e < N_EDGES) {
        s = edge_val(ei, e);
        d = edge_val(ei, (long long)N_EDGES + e);
    } else {
        s = d = e - N_EDGES;
    }
    int p = atomicAdd(&g_cursor[d], 1);
    g_srcs[p] = s;
}

// ---------------- encoder MLP: 8 -> 32 (elu) -> 64 (elu) ----------------
__global__ void k_encoder(const float* __restrict__ x,
                          const float* __restrict__ W1, const float* __restrict__ b1,
                          const float* __restrict__ W2, const float* __restrict__ b2,
                          float* __restrict__ hout) {
    __shared__ float sW1[8 * 32], sb1[32], sW2[32 * 64], sb2[64];
    for (int i = threadIdx.x; i < 8 * 32; i += blockDim.x) sW1[i] = W1[i];
    for (int i = threadIdx.x; i < 32; i += blockDim.x) sb1[i] = b1[i];
    for (int i = threadIdx.x; i < 32 * 64; i += blockDim.x) sW2[i] = W2[i];
    for (int i = threadIdx.x; i < 64; i += blockDim.x) sb2[i] = b2[i];
    __syncthreads();
    int n = blockIdx.x * blockDim.x + threadIdx.x;
    if (n >= N_NODES) return;
    float xi[8];
#pragma unroll
    for (int i = 0; i < 8; i++) xi[i] = x[n * 8 + i];
    float hid[32];
#pragma unroll
    for (int j = 0; j < 32; j++) {
        float a = sb1[j];
#pragma unroll
        for (int i = 0; i < 8; i++) a += xi[i] * sW1[i * 32 + j];
        hid[j] = eluf(a);
    }
    for (int j = 0; j < 64; j++) {
        float a = sb2[j];
#pragma unroll
        for (int i = 0; i < 32; i++) a += hid[i] * sW2[i * 64 + j];
        hout[n * 64 + j] = eluf(a);
    }
}

// ---------------- projection GEMM [N,64]@[64,256] -> fp16, f32x2 packed ----------------
// block: 64 rows x 128 cols, 256 threads, thread = 8 rows x 4 cols
__global__ void __launch_bounds__(256) k_gemm(const float* __restrict__ hin,
                                              const float* __restrict__ W,
                                              __half* __restrict__ hout) {
    __shared__ float sW[64 * 128];
    __shared__ float sXT[64 * 68];  // [k][r], pad 68 keeps 16B alignment per k-row
    int row0 = blockIdx.x * 64;
    int colbase = blockIdx.y * 128;
    for (int i = threadIdx.x; i < 2048; i += 256) {
        int k = i >> 5, c4 = (i & 31) * 4;
        *(float4*)&sW[k * 128 + c4] = *(const float4*)&W[k * 256 + colbase + c4];
    }
    for (int i = threadIdx.x; i < 1024; i += 256) {
        int r = i >> 4, k0 = (i & 15) * 4;
        float4 v = make_float4(0.f, 0.f, 0.f, 0.f);
        if (row0 + r < N_NODES) v = *(const float4*)&hin[(row0 + r) * 64 + k0];
        sXT[(k0 + 0) * 68 + r] = v.x;
        sXT[(k0 + 1) * 68 + r] = v.y;
        sXT[(k0 + 2) * 68 + r] = v.z;
        sXT[(k0 + 3) * 68 + r] = v.w;
    }
    __syncthreads();
    int cg = threadIdx.x & 31;
    int rg = threadIdx.x >> 5;
    int c0 = cg * 4, r0 = rg * 8;
    unsigned long long acc[4][4];
#pragma unroll
    for (int a = 0; a < 4; a++)
#pragma unroll
        for (int b = 0; b < 4; b++) acc[a][b] = 0ull;
    unsigned xb = (unsigned)__cvta_generic_to_shared(&sXT[r0]);
#pragma unroll 4
    for (int k = 0; k < 64; k++) {
        unsigned long long xp[4];
        asm("ld.shared.v2.u64 {%0,%1},[%2];" : "=l"(xp[0]), "=l"(xp[1]) : "r"(xb + k * 272));
        asm("ld.shared.v2.u64 {%0,%1},[%2];" : "=l"(xp[2]), "=l"(xp[3]) : "r"(xb + k * 272 + 16));
        float4 wv = *(float4*)&sW[k * 128 + c0];
        unsigned long long wd[4] = {pack2(wv.x, wv.x), pack2(wv.y, wv.y),
                                    pack2(wv.z, wv.z), pack2(wv.w, wv.w)};
#pragma unroll
        for (int rp = 0; rp < 4; rp++)
#pragma unroll
            for (int c = 0; c < 4; c++) fma2(acc[rp][c], xp[rp], wd[c]);
    }
#pragma unroll
    for (int rp = 0; rp < 4; rp++) {
        float2 f0 = unpk2(acc[rp][0]), f1 = unpk2(acc[rp][1]);
        float2 f2 = unpk2(acc[rp][2]), f3 = unpk2(acc[rp][3]);
        int rA = row0 + r0 + 2 * rp;
        if (rA < N_NODES) {
            __half2 a = __floats2half2_rn(f0.x, f1.x), b = __floats2half2_rn(f2.x, f3.x);
            uint2 st;
            st.x = *(unsigned*)&a;
            st.y = *(unsigned*)&b;
            *(uint2*)&hout[(long long)rA * 256 + colbase + c0] = st;
        }
        if (rA + 1 < N_NODES) {
            __half2 a = __floats2half2_rn(f0.y, f1.y), b = __floats2half2_rn(f2.y, f3.y);
            uint2 st;
            st.x = *(unsigned*)&a;
            st.y = *(unsigned*)&b;
            *(uint2*)&hout[(long long)(rA + 1) * 256 + colbase + c0] = st;
        }
    }
}

// ---------------- attention coefficients ----------------
__global__ void k_att(const __half* __restrict__ hp,
                      const float* __restrict__ as, const float* __restrict__ ad,
                      float* __restrict__ asrc, float* __restrict__ adst) {
    int warp = (blockIdx.x * blockDim.x + threadIdx.x) >> 5;
    int lane = threadIdx.x & 31;
    if (warp >= N_NODES) return;
    uint4 q = *((const uint4*)(hp + (long long)warp * 256) + lane);
    float2 f0 = __half22float2(*(__half2*)&q.x);
    float2 f1 = __half22float2(*(__half2*)&q.y);
    float2 f2 = __half22float2(*(__half2*)&q.z);
    float2 f3 = __half22float2(*(__half2*)&q.w);
    int head = lane >> 3;
    int off = head * 64 + (lane & 7) * 8;
    const float4* ap = (const float4*)(as + off);
    float4 a0 = ap[0], a1 = ap[1];
    const float4* dp = (const float4*)(ad + off);
    float4 d0 = dp[0], d1 = dp[1];
    float ps = f0.x * a0.x + f0.y * a0.y + f1.x * a0.z + f1.y * a0.w +
               f2.x * a1.x + f2.y * a1.y + f3.x * a1.z + f3.y * a1.w;
    float pd = f0.x * d0.x + f0.y * d0.y + f1.x * d0.z + f1.y * d0.w +
               f2.x * d1.x + f2.y * d1.y + f3.x * d1.z + f3.y * d1.w;
#pragma unroll
    for (int o = 4; o >= 1; o >>= 1) {
        ps += __shfl_down_sync(0xffffffffu, ps, o);
        pd += __shfl_down_sync(0xffffffffu, pd, o);
    }
    if ((lane & 7) == 0) {
        asrc[warp * 4 + head] = ps;
        adst[warp * 4 + head] = pd;
    }
}

// ---------------- aggregation: warp per dst node, fp16 gather + f32x2 ----------------
__global__ void k_agg(const float* __restrict__ bias,
                      const float* __restrict__ hin, float* __restrict__ hout,
                      const __half* __restrict__ hp) {
    __shared__ int   s_src[8][32];
    __shared__ float s_e[8][32][4];
    int wib = threadIdx.x >> 5;
    int lane = threadIdx.x & 31;
    int d = blockIdx.x * 8 + wib;
    if (d >= N_NODES) return;
    int start = g_off[d], end = g_off[d + 1];
    float4 adst = *(const float4*)(g_adst + d * 4);

    float m0 = -1e30f, m1 = -1e30f, m2 = -1e30f, m3 = -1e30f;
    for (int i = start + lane; i < end; i += 32) {
        int s = g_srcs[i];
        float4 a = *(const float4*)(g_asrc + s * 4);
        m0 = fmaxf(m0, lrelu(a.x + adst.x));
        m1 = fmaxf(m1, lrelu(a.y + adst.y));
        m2 = fmaxf(m2, lrelu(a.z + adst.z));
        m3 = fmaxf(m3, lrelu(a.w + adst.w));
    }
#pragma unroll
    for (int o = 16; o; o >>= 1) {
        m0 = fmaxf(m0, __shfl_xor_sync(0xffffffffu, m0, o));
        m1 = fmaxf(m1, __shfl_xor_sync(0xffffffffu, m1, o));
        m2 = fmaxf(m2, __shfl_xor_sync(0xffffffffu, m2, o));
        m3 = fmaxf(m3, __shfl_xor_sync(0xffffffffu, m3, o));
    }

    int head = lane >> 3;
    unsigned long long acc2[4] = {0ull, 0ull, 0ull, 0ull};
    float den0 = 0.f, den1 = 0.f, den2 = 0.f, den3 = 0.f;
    const uint4* hp4 = (const uint4*)hp;

    for (int base = start; base < end; base += 32) {
        int i = base + lane;
        int cnt = min(32, end - base);
        if (i < end) {
            int s = g_srcs[i];
            float4 a = *(const float4*)(g_asrc + s * 4);
            float e0 = __expf(lrelu(a.x + adst.x) - m0);
            float e1 = __expf(lrelu(a.y + adst.y) - m1);
            float e2 = __expf(lrelu(a.z + adst.z) - m2);
            float e3 = __expf(lrelu(a.w + adst.w) - m3);
            den0 += e0; den1 += e1; den2 += e2; den3 += e3;
            s_src[wib][lane] = s;
            s_e[wib][lane][0] = e0;
            s_e[wib][lane][1] = e1;
            s_e[wib][lane][2] = e2;
            s_e[wib][lane][3] = e3;
        }
        __syncwarp();
        for (int k = 0; k < cnt; k++) {
            int s = s_src[wib][k];
            float eh = s_e[wib][k][head];
            unsigned long long ep = pack2(eh, eh);
            uint4 raw = __ldg(&hp4[(long long)s * 32 + lane]);
            float2 g0 = __half22float2(*(__half2*)&raw.x);
            float2 g1 = __half22float2(*(__half2*)&raw.y);
            float2 g2 = __half22float2(*(__half2*)&raw.z);
            float2 g3 = __half22float2(*(__half2*)&raw.w);
            fma2(acc2[0], ep, pack2(g0.x, g0.y));
            fma2(acc2[1], ep, pack2(g1.x, g1.y));
            fma2(acc2[2], ep, pack2(g2.x, g2.y));
            fma2(acc2[3], ep, pack2(g3.x, g3.y));
        }
        __syncwarp();
    }

#pragma unroll
    for (int o = 16; o; o >>= 1) {
        den0 += __shfl_xor_sync(0xffffffffu, den0, o);
        den1 += __shfl_xor_sync(0xffffffffu, den1, o);
        den2 += __shfl_xor_sync(0xffffffffu, den2, o);
        den3 += __shfl_xor_sync(0xffffffffu, den3, o);
    }
    float dh = (head == 0) ? den0 : (head == 1) ? den1 : (head == 2) ? den2 : den3;
    float inv = 1.f / (dh + 1e-16f);
    float acc[8];
#pragma unroll
    for (int j = 0; j < 4; j++) {
        float2 f = unpk2(acc2[j]);
        acc[2 * j] = f.x * inv;
        acc[2 * j + 1] = f.y * inv;
    }
#pragma unroll
    for (int j = 0; j < 8; j++) {
        acc[j] += __shfl_xor_sync(0xffffffffu, acc[j], 8);
        acc[j] += __shfl_xor_sync(0xffffffffu, acc[j], 16);
    }
    if (lane < 8) {
#pragma unroll
        for (int j = 0; j < 8; j++) {
            int cc = lane * 8 + j;
            hout[d * 64 + cc] = 0.25f * acc[j] + bias[cc] + hin[d * 64 + cc];
        }
    }
}

// ---------------- output MLP: 64 nodes per block ----------------
__global__ void k_outmlp(const float* __restrict__ hin,
                         const float* __restrict__ W1, const float* __restrict__ b1,
                         const float* __restrict__ W2, const float* __restrict__ b2,
                         const float* __restrict__ W3, const float* __restrict__ b3,
                         float* __restrict__ out) {
    __shared__ float sW1[64 * 64], sW2[64 * 32], sW3[32 * 8];
    __shared__ float sb1[64], sb2[32], sb3[8];
    __shared__ float sh[8][64], sh1[8][64], sh2[8][32];
    for (int i = threadIdx.x; i < 64 * 64; i += blockDim.x) sW1[i] = W1[i];
    for (int i = threadIdx.x; i < 64 * 32; i += blockDim.x) sW2[i] = W2[i];
    for (int i = threadIdx.x; i < 32 * 8; i += blockDim.x) sW3[i] = W3[i];
    for (int i = threadIdx.x; i < 64; i += blockDim.x) sb1[i] = b1[i];
    for (int i = threadIdx.x; i < 32; i += blockDim.x) sb2[i] = b2[i];
    for (int i = threadIdx.x; i < 8; i += blockDim.x) sb3[i] = b3[i];
    __syncthreads();
    int wib = threadIdx.x >> 5;
    int lane = threadIdx.x & 31;
    for (int nd = 0; nd < 8; nd++) {
        int d = blockIdx.x * 64 + wib * 8 + nd;
        if (d >= N_NODES) continue;
        sh[wib][lane] = hin[d * 64 + lane];
        sh[wib][lane + 32] = hin[d * 64 + lane + 32];
        __syncwarp();
        float a0 = sb1[lane], a1 = sb1[lane + 32];
#pragma unroll
        for (int i = 0; i < 64; i++) {
            float xv = sh[wib][i];
            a0 += xv * sW1[i * 64 + lane];
            a1 += xv * sW1[i * 64 + lane + 32];
        }
        sh1[wib][lane] = eluf(a0);
        sh1[wib][lane + 32] = eluf(a1);
        __syncwarp();
        float a = sb2[lane];
#pragma unroll
        for (int i = 0; i < 64; i++) a += sh1[wib][i] * sW2[i * 32 + lane];
        sh2[wib][lane] = eluf(a);
        __syncwarp();
        if (lane < 8) {
            float o = sb3[lane];
#pragma unroll
            for (int i = 0; i < 32; i++) o += sh2[wib][i] * sW3[i * 8 + lane];
            out[d * 8 + lane] = o;
        }
        __syncwarp();
    }
}

// ---------------- launch ----------------
extern "C" void kernel_launch(void* const* d_in, const int* in_sizes, int n_in,
                              void* d_out, int out_size) {
    const float* x      = (const float*)d_in[0];
    const void*  ei     = d_in[1];
    const float* W_enc1 = (const float*)d_in[2];
    const float* b_enc1 = (const float*)d_in[3];
    const float* W_enc2 = (const float*)d_in[4];
    const float* b_enc2 = (const float*)d_in[5];
    const float* W_g[3] = {(const float*)d_in[6],  (const float*)d_in[10], (const float*)d_in[14]};
    const float* as_[3] = {(const float*)d_in[7],  (const float*)d_in[11], (const float*)d_in[15]};
    const float* ad_[3] = {(const float*)d_in[8],  (const float*)d_in[12], (const float*)d_in[16]};
    const float* bg_[3] = {(const float*)d_in[9],  (const float*)d_in[13], (const float*)d_in[17]};
    const float* W_o1 = (const float*)d_in[18];
    const float* b_o1 = (const float*)d_in[19];
    const float* W_o2 = (const float*)d_in[20];
    const float* b_o2 = (const float*)d_in[21];
    const float* W_o3 = (const float*)d_in[22];
    const float* b_o3 = (const float*)d_in[23];
    float* out = (float*)d_out;

    static bool inited = false;
    static cudaStream_t sB;
    static cudaEvent_t evF, evJ;
    static float* hA_p = nullptr;
    static float* hB_p = nullptr;
    static __half* hp_p = nullptr;
    static float* asrc_p = nullptr;
    static float* adst_p = nullptr;
    if (!inited) {
        cudaStreamCreateWithFlags(&sB, cudaStreamNonBlocking);
        cudaEventCreateWithFlags(&evF, cudaEventDisableTiming);
        cudaEventCreateWithFlags(&evJ, cudaEventDisableTiming);
        cudaGetSymbolAddress((void**)&hA_p, g_hA);
        cudaGetSymbolAddress((void**)&hB_p, g_hB);
        cudaGetSymbolAddress((void**)&hp_p, g_hproj);
        cudaGetSymbolAddress((void**)&asrc_p, g_asrc);
        cudaGetSymbolAddress((void**)&adst_p, g_adst);
        inited = true;
    }
    cudaStream_t s0 = 0;

    // fork: side stream does encoder + layer-1 dense work while stream 0 builds CSR
    cudaEventRecord(evF, s0);
    cudaStreamWaitEvent(sB, evF, 0);

    // stream 0: CSR build
    k_init<<<NB_SCAN, 256, 0, s0>>>((const int*)ei);
    k_count<<<(N_EDGES + 255) / 256, 256, 0, s0>>>(ei);
    k_scan1<<<NB_SCAN, 256, 0, s0>>>();
    k_scan2<<<1, 128, 0, s0>>>();
    k_scan3<<<NB_SCAN, 256, 0, s0>>>();
    k_scatter<<<(TOT_EDGES + 255) / 256, 256, 0, s0>>>(ei);

    dim3 ggrid((N_NODES + 63) / 64, 2);

    // side stream: encoder + layer-1 projection + attention coeffs
    k_encoder<<<NB_SCAN, 256, 0, sB>>>(x, W_enc1, b_enc1, W_enc2, b_enc2, hA_p);
    k_gemm<<<ggrid, 256, 0, sB>>>(hA_p, W_g[0], hp_p);
    k_att<<<(N_NODES + 7) / 8, 256, 0, sB>>>(hp_p, as_[0], ad_[0], asrc_p, adst_p);

    // join
    cudaEventRecord(evJ, sB);
    cudaStreamWaitEvent(s0, evJ, 0);

    // layer 1 aggregate, then layers 2-3 serial on stream 0
    k_agg<<<(N_NODES + 7) / 8, 256, 0, s0>>>(bg_[0], hA_p, hB_p, hp_p);

    k_gemm<<<ggrid, 256, 0, s0>>>(hB_p, W_g[1], hp_p);
    k_att<<<(N_NODES + 7) / 8, 256, 0, s0>>>(hp_p, as_[1], ad_[1], asrc_p, adst_p);
    k_agg<<<(N_NODES + 7) / 8, 256, 0, s0>>>(bg_[1], hB_p, hA_p, hp_p);

    k_gemm<<<ggrid, 256, 0, s0>>>(hA_p, W_g[2], hp_p);
    k_att<<<(N_NODES + 7) / 8, 256, 0, s0>>>(hp_p, as_[2], ad_[2], asrc_p, adst_p);
    k_agg<<<(N_NODES + 7) / 8, 256, 0, s0>>>(bg_[2], hA_p, hB_p, hp_p);

    k_outmlp<<<(N_NODES + 63) / 64, 256, 0, s0>>>(hB_p, W_o1, b_o1, W_o2, b_o2, W_o3, b_o3, out);

    (void)in_sizes; (void)n_in; (void)out_size;
}

// round 7
// speedup vs baseline: 1.5345x; 1.2628x over previous
#include <cuda_runtime.h>
#include <cuda_fp16.h>
#include <math.h>

#define N_NODES 20000
#define N_EDGES 320000
#define TOT_EDGES (N_EDGES + N_NODES)
#define HID 64
#define NH 4
#define FDIM 256
#define NB_SCAN 79  // ceil(20000/256)

// ---------------- scratch ----------------
__device__ float  g_hA[N_NODES * HID];
__device__ float  g_hB[N_NODES * HID];
__device__ __half g_hproj[N_NODES * FDIM];
__device__ float  g_asrc[N_NODES * NH];
__device__ float  g_adst[N_NODES * NH];
__device__ int    g_deg[N_NODES];
__device__ int    g_off[N_NODES + 1];
__device__ int    g_cursor[N_NODES];
__device__ int    g_srcs[TOT_EDGES];
__device__ int    g_bsum[NB_SCAN];
__device__ int    g_is64;

__device__ __forceinline__ float eluf(float x) { return x > 0.f ? x : (__expf(x) - 1.f); }
__device__ __forceinline__ float lrelu(float x) { return x > 0.f ? x : 0.2f * x; }

__device__ __forceinline__ unsigned long long pack2(float a, float b) {
    unsigned long long r;
    asm("mov.b64 %0,{%1,%2};" : "=l"(r) : "f"(a), "f"(b));
    return r;
}
__device__ __forceinline__ float2 unpk2(unsigned long long v) {
    float2 r;
    asm("mov.b64 {%0,%1},%2;" : "=f"(r.x), "=f"(r.y) : "l"(v));
    return r;
}
__device__ __forceinline__ void fma2(unsigned long long& d, unsigned long long a, unsigned long long b) {
    asm("fma.rn.f32x2 %0,%1,%2,%0;" : "+l"(d) : "l"(a), "l"(b));
}
__device__ __forceinline__ unsigned long long add2(unsigned long long a, unsigned long long b) {
    unsigned long long r;
    asm("add.rn.f32x2 %0,%1,%2;" : "=l"(r) : "l"(a), "l"(b));
    return r;
}

// ---------------- edge dtype detect ----------------
__global__ void k_detect(const int* ei_words) {
    __shared__ int any;
    if (threadIdx.x == 0) any = 0;
    __syncthreads();
    int found = 0;
    for (int j = 1 + 2 * threadIdx.x; j < 2048; j += 2 * blockDim.x)
        if (ei_words[j] != 0) found = 1;
    if (found) atomicOr(&any, 1);
    __syncthreads();
    if (threadIdx.x == 0) g_is64 = any ? 0 : 1;
}

__device__ __forceinline__ int edge_val(const void* ei, long long idx) {
    if (g_is64) return (int)((const long long*)ei)[idx];
    return ((const int*)ei)[idx];
}

__global__ void k_count(const void* ei) {
    int e = blockIdx.x * blockDim.x + threadIdx.x;
    if (e >= N_EDGES) return;
    int d = edge_val(ei, (long long)N_EDGES + e);
    atomicAdd(&g_deg[d], 1);
}

// ---------------- scan: per-block local + fold base sum into pass 2 ----------------
__global__ void k_scan1() {
    int t = threadIdx.x;
    int i = blockIdx.x * 256 + t;
    int v = (i < N_NODES) ? (g_deg[i] + 1) : 0;  // +1 = self loop
    int lane = t & 31, w = t >> 5;
    int s = v;
#pragma unroll
    for (int o = 1; o < 32; o <<= 1) {
        int u = __shfl_up_sync(0xffffffffu, s, o);
        if (lane >= o) s += u;
    }
    __shared__ int wsum[8];
    if (lane == 31) wsum[w] = s;
    __syncthreads();
    if (w == 0 && lane < 8) {
        int xv = wsum[lane];
#pragma unroll
        for (int o = 1; o < 8; o <<= 1) {
            int u = __shfl_up_sync(0xffu, xv, o);
            if (lane >= o) xv += u;
        }
        wsum[lane] = xv;
    }
    __syncthreads();
    int base = (w > 0) ? wsum[w - 1] : 0;
    if (i < N_NODES) g_off[i] = base + s - v;  // block-local exclusive
    if (t == 0) g_bsum[blockIdx.x] = wsum[7];
}

__global__ void k_scan3() {
    __shared__ int sbase;
    int bid = blockIdx.x;
    if (threadIdx.x < 32) {
        int s = 0;
        for (int j = threadIdx.x; j < bid; j += 32) s += g_bsum[j];
#pragma unroll
        for (int o = 16; o; o >>= 1) s += __shfl_xor_sync(0xffffffffu, s, o);
        if (threadIdx.x == 0) sbase = s;
    }
    __syncthreads();
    int i = bid * 256 + threadIdx.x;
    if (i < N_NODES) {
        int off = g_off[i] + sbase;
        g_off[i] = off;
        g_cursor[i] = off;
    }
    if (i == 0) g_off[N_NODES] = TOT_EDGES;
}

__global__ void k_scatter(const void* ei) {
    int e = blockIdx.x * blockDim.x + threadIdx.x;
    if (e >= TOT_EDGES) return;
    int s, d;
    if (e < N_EDGES) {
        s = edge_val(ei, e);
        d = edge_val(ei, (long long)N_EDGES + e);
    } else {
        s = d = e - N_EDGES;
    }
    int p = atomicAdd(&g_cursor[d], 1);
    g_srcs[p] = s;
}

// =======================================================================
// GEMM [N,64]@[64,256] -> fp16 hproj, with fused attention-coefficient
// epilogue (each 128-col block holds 2 complete heads).
// block: 64 rows x 128 cols, 256 threads, thread = 8 rows x 4 cols (f32x2 pairs)
// =======================================================================
__device__ __forceinline__ void gemm_core_and_att(
    int row0, int colbase,
    const float* __restrict__ W,
    __half* __restrict__ hout,
    float* __restrict__ asrc, float* __restrict__ adst,
    float* sW, float* sXT, float* sAs, float* sAd)
{
    int cg = threadIdx.x & 31;
    int rg = threadIdx.x >> 5;
    int c0 = cg * 4, r0 = rg * 8;
    unsigned long long acc[4][4];
#pragma unroll
    for (int a = 0; a < 4; a++)
#pragma unroll
        for (int b = 0; b < 4; b++) acc[a][b] = 0ull;
    unsigned xb = (unsigned)__cvta_generic_to_shared(&sXT[r0]);
#pragma unroll 4
    for (int k = 0; k < 64; k++) {
        unsigned long long xp[4];
        asm("ld.shared.v2.u64 {%0,%1},[%2];" : "=l"(xp[0]), "=l"(xp[1]) : "r"(xb + k * 272));
        asm("ld.shared.v2.u64 {%0,%1},[%2];" : "=l"(xp[2]), "=l"(xp[3]) : "r"(xb + k * 272 + 16));
        float4 wv = *(float4*)&sW[k * 128 + c0];
        unsigned long long wd[4] = {pack2(wv.x, wv.x), pack2(wv.y, wv.y),
                                    pack2(wv.z, wv.z), pack2(wv.w, wv.w)};
#pragma unroll
        for (int rp = 0; rp < 4; rp++)
#pragma unroll
            for (int c = 0; c < 4; c++) fma2(acc[rp][c], xp[rp], wd[c]);
    }

    // ---- store fp16 hproj ----
#pragma unroll
    for (int rp = 0; rp < 4; rp++) {
        float2 f0 = unpk2(acc[rp][0]), f1 = unpk2(acc[rp][1]);
        float2 f2 = unpk2(acc[rp][2]), f3 = unpk2(acc[rp][3]);
        int rA = row0 + r0 + 2 * rp;
        if (rA < N_NODES) {
            __half2 a = __floats2half2_rn(f0.x, f1.x), b = __floats2half2_rn(f2.x, f3.x);
            uint2 st;
            st.x = *(unsigned*)&a;
            st.y = *(unsigned*)&b;
            *(uint2*)&hout[(long long)rA * 256 + colbase + c0] = st;
        }
        if (rA + 1 < N_NODES) {
            __half2 a = __floats2half2_rn(f0.y, f1.y), b = __floats2half2_rn(f2.y, f3.y);
            uint2 st;
            st.x = *(unsigned*)&a;
            st.y = *(unsigned*)&b;
            *(uint2*)&hout[(long long)(rA + 1) * 256 + colbase + c0] = st;
        }
    }

    // ---- fused attention coefficients ----
    int headLocal = cg >> 4;            // 0: lanes 0-15 (cols 0-63), 1: lanes 16-31
    int chBase = c0 & 63;
    float asv[4], adv[4];
#pragma unroll
    for (int c = 0; c < 4; c++) {
        asv[c] = sAs[headLocal * 64 + chBase + c];
        adv[c] = sAd[headLocal * 64 + chBase + c];
    }
    unsigned long long ps[4], pd[4];
#pragma unroll
    for (int rp = 0; rp < 4; rp++) { ps[rp] = 0ull; pd[rp] = 0ull; }
#pragma unroll
    for (int rp = 0; rp < 4; rp++)
#pragma unroll
        for (int c = 0; c < 4; c++) {
            fma2(ps[rp], acc[rp][c], pack2(asv[c], asv[c]));
            fma2(pd[rp], acc[rp][c], pack2(adv[c], adv[c]));
        }
#pragma unroll
    for (int o = 1; o < 16; o <<= 1) {
#pragma unroll
        for (int rp = 0; rp < 4; rp++) {
            ps[rp] = add2(ps[rp], __shfl_xor_sync(0xffffffffu, ps[rp], o));
            pd[rp] = add2(pd[rp], __shfl_xor_sync(0xffffffffu, pd[rp], o));
        }
    }
    if ((cg & 15) == 0) {
        int hg = (colbase >> 6) + headLocal;  // global head
#pragma unroll
        for (int rp = 0; rp < 4; rp++) {
            int rA = row0 + r0 + 2 * rp;
            float2 v = unpk2(ps[rp]);
            float2 w = unpk2(pd[rp]);
            if (rA < N_NODES) { asrc[rA * 4 + hg] = v.x; adst[rA * 4 + hg] = w.x; }
            if (rA + 1 < N_NODES) { asrc[(rA + 1) * 4 + hg] = v.y; adst[(rA + 1) * 4 + hg] = w.y; }
        }
    }
}

// layers 2,3: read hin from global
__global__ void __launch_bounds__(256) k_gemm_att(
    const float* __restrict__ hin, const float* __restrict__ W,
    const float* __restrict__ as_, const float* __restrict__ ad_,
    __half* __restrict__ hout, float* __restrict__ asrc, float* __restrict__ adst)
{
    __shared__ float sW[64 * 128];
    __shared__ float sXT[64 * 68];
    __shared__ float sAs[128], sAd[128];
    int row0 = blockIdx.x * 64;
    int colbase = blockIdx.y * 128;
    for (int i = threadIdx.x; i < 2048; i += 256) {
        int k = i >> 5, c4 = (i & 31) * 4;
        *(float4*)&sW[k * 128 + c4] = *(const float4*)&W[k * 256 + colbase + c4];
    }
    if (threadIdx.x < 128) {
        sAs[threadIdx.x] = as_[colbase + threadIdx.x];
        sAd[threadIdx.x] = ad_[colbase + threadIdx.x];
    }
    for (int i = threadIdx.x; i < 1024; i += 256) {
        int r = i >> 4, k0 = (i & 15) * 4;
        float4 v = make_float4(0.f, 0.f, 0.f, 0.f);
        if (row0 + r < N_NODES) v = *(const float4*)&hin[(row0 + r) * 64 + k0];
        sXT[(k0 + 0) * 68 + r] = v.x;
        sXT[(k0 + 1) * 68 + r] = v.y;
        sXT[(k0 + 2) * 68 + r] = v.z;
        sXT[(k0 + 3) * 68 + r] = v.w;
    }
    __syncthreads();
    gemm_core_and_att(row0, colbase, W, hout, asrc, adst, sW, sXT, sAs, sAd);
}

// layer 1: fused encoder MLP 8->32(elu)->64(elu), then GEMM+att
__global__ void __launch_bounds__(256) k_gemm_enc(
    const float* __restrict__ x,
    const float* __restrict__ We1, const float* __restrict__ be1,
    const float* __restrict__ We2, const float* __restrict__ be2,
    const float* __restrict__ W,
    const float* __restrict__ as_, const float* __restrict__ ad_,
    __half* __restrict__ hout, float* __restrict__ asrc, float* __restrict__ adst,
    float* __restrict__ hA)
{
    __shared__ float sW[64 * 128];
    __shared__ float sXT[64 * 68];
    __shared__ float sAs[128], sAd[128];
    __shared__ float sE1[8 * 32], sB1[32], sE2[32 * 64], sB2[64];
    int row0 = blockIdx.x * 64;
    int colbase = blockIdx.y * 128;
    for (int i = threadIdx.x; i < 2048; i += 256) {
        int k = i >> 5, c4 = (i & 31) * 4;
        *(float4*)&sW[k * 128 + c4] = *(const float4*)&W[k * 256 + colbase + c4];
    }
    if (threadIdx.x < 128) {
        sAs[threadIdx.x] = as_[colbase + threadIdx.x];
        sAd[threadIdx.x] = ad_[colbase + threadIdx.x];
    }
    for (int i = threadIdx.x; i < 256; i += 256) sE1[i] = We1[i];
    if (threadIdx.x < 32) sB1[threadIdx.x] = be1[threadIdx.x];
    for (int i = threadIdx.x; i < 2048; i += 256) sE2[i] = We2[i];
    if (threadIdx.x < 64) sB2[threadIdx.x] = be2[threadIdx.x];
    __syncthreads();

    // encoder: thread = (row r, quarter q); computes 16 of 64 outputs for its row
    {
        int rr = threadIdx.x >> 2;
        int q = threadIdx.x & 3;
        int n = row0 + rr;
        float outv[16];
        if (n < N_NODES) {
            float4 xa = *(const float4*)&x[n * 8];
            float4 xb = *(const float4*)&x[n * 8 + 4];
            float xi[8] = {xa.x, xa.y, xa.z, xa.w, xb.x, xb.y, xb.z, xb.w};
            float hid[32];
#pragma unroll
            for (int j = 0; j < 32; j++) {
                float a = sB1[j];
#pragma unroll
                for (int i = 0; i < 8; i++) a += xi[i] * sE1[i * 32 + j];
                hid[j] = eluf(a);
            }
#pragma unroll
            for (int j = 0; j < 16; j++) {
                int jj = q * 16 + j;
                float a = sB2[jj];
#pragma unroll
                for (int i = 0; i < 32; i++) a += hid[i] * sE2[i * 64 + jj];
                outv[j] = eluf(a);
            }
        } else {
#pragma unroll
            for (int j = 0; j < 16; j++) outv[j] = 0.f;
        }
#pragma unroll
        for (int j = 0; j < 16; j++) sXT[(q * 16 + j) * 68 + rr] = outv[j];
        if (blockIdx.y == 0 && n < N_NODES) {
#pragma unroll
            for (int j = 0; j < 16; j += 4)
                *(float4*)&hA[n * 64 + q * 16 + j] =
                    make_float4(outv[j], outv[j + 1], outv[j + 2], outv[j + 3]);
        }
    }
    __syncthreads();
    gemm_core_and_att(row0, colbase, W, hout, asrc, adst, sW, sXT, sAs, sAd);
}

// ---------------- aggregation: warp per dst node, fp16 gather + f32x2 ----------------
__global__ void k_agg(const float* __restrict__ bias,
                      const float* __restrict__ hin, float* __restrict__ hout,
                      const __half* __restrict__ hp) {
    __shared__ int   s_src[8][32];
    __shared__ float s_e[8][32][4];
    int wib = threadIdx.x >> 5;
    int lane = threadIdx.x & 31;
    int d = blockIdx.x * 8 + wib;
    if (d >= N_NODES) return;
    int start = g_off[d], end = g_off[d + 1];
    float4 adst = *(const float4*)(g_adst + d * 4);

    float m0 = -1e30f, m1 = -1e30f, m2 = -1e30f, m3 = -1e30f;
    for (int i = start + lane; i < end; i += 32) {
        int s = g_srcs[i];
        float4 a = *(const float4*)(g_asrc + s * 4);
        m0 = fmaxf(m0, lrelu(a.x + adst.x));
        m1 = fmaxf(m1, lrelu(a.y + adst.y));
        m2 = fmaxf(m2, lrelu(a.z + adst.z));
        m3 = fmaxf(m3, lrelu(a.w + adst.w));
    }
#pragma unroll
    for (int o = 16; o; o >>= 1) {
        m0 = fmaxf(m0, __shfl_xor_sync(0xffffffffu, m0, o));
        m1 = fmaxf(m1, __shfl_xor_sync(0xffffffffu, m1, o));
        m2 = fmaxf(m2, __shfl_xor_sync(0xffffffffu, m2, o));
        m3 = fmaxf(m3, __shfl_xor_sync(0xffffffffu, m3, o));
    }

    int head = lane >> 3;
    unsigned long long acc2[4] = {0ull, 0ull, 0ull, 0ull};
    float den0 = 0.f, den1 = 0.f, den2 = 0.f, den3 = 0.f;
    const uint4* hp4 = (const uint4*)hp;

    for (int base = start; base < end; base += 32) {
        int i = base + lane;
        int cnt = min(32, end - base);
        if (i < end) {
            int s = g_srcs[i];
            float4 a = *(const float4*)(g_asrc + s * 4);
            float e0 = __expf(lrelu(a.x + adst.x) - m0);
            float e1 = __expf(lrelu(a.y + adst.y) - m1);
            float e2 = __expf(lrelu(a.z + adst.z) - m2);
            float e3 = __expf(lrelu(a.w + adst.w) - m3);
            den0 += e0; den1 += e1; den2 += e2; den3 += e3;
            s_src[wib][lane] = s;
            s_e[wib][lane][0] = e0;
            s_e[wib][lane][1] = e1;
            s_e[wib][lane][2] = e2;
            s_e[wib][lane][3] = e3;
        }
        __syncwarp();
#pragma unroll 2
        for (int k = 0; k < cnt; k++) {
            int s = s_src[wib][k];
            float eh = s_e[wib][k][head];
            unsigned long long ep = pack2(eh, eh);
            uint4 raw = __ldg(&hp4[(long long)s * 32 + lane]);
            float2 g0 = __half22float2(*(__half2*)&raw.x);
            float2 g1 = __half22float2(*(__half2*)&raw.y);
            float2 g2 = __half22float2(*(__half2*)&raw.z);
            float2 g3 = __half22float2(*(__half2*)&raw.w);
            fma2(acc2[0], ep, pack2(g0.x, g0.y));
            fma2(acc2[1], ep, pack2(g1.x, g1.y));
            fma2(acc2[2], ep, pack2(g2.x, g2.y));
            fma2(acc2[3], ep, pack2(g3.x, g3.y));
        }
        __syncwarp();
    }

#pragma unroll
    for (int o = 16; o; o >>= 1) {
        den0 += __shfl_xor_sync(0xffffffffu, den0, o);
        den1 += __shfl_xor_sync(0xffffffffu, den1, o);
        den2 += __shfl_xor_sync(0xffffffffu, den2, o);
        den3 += __shfl_xor_sync(0xffffffffu, den3, o);
    }
    float dh = (head == 0) ? den0 : (head == 1) ? den1 : (head == 2) ? den2 : den3;
    float inv = 1.f / (dh + 1e-16f);
    float acc[8];
#pragma unroll
    for (int j = 0; j < 4; j++) {
        float2 f = unpk2(acc2[j]);
        acc[2 * j] = f.x * inv;
        acc[2 * j + 1] = f.y * inv;
    }
#pragma unroll
    for (int j = 0; j < 8; j++) {
        acc[j] += __shfl_xor_sync(0xffffffffu, acc[j], 8);
        acc[j] += __shfl_xor_sync(0xffffffffu, acc[j], 16);
    }
    if (lane < 8) {
#pragma unroll
        for (int j = 0; j < 8; j++) {
            int cc = lane * 8 + j;
            hout[d * 64 + cc] = 0.25f * acc[j] + bias[cc] + hin[d * 64 + cc];
        }
    }
}

// ---------------- output MLP: 64 nodes per block ----------------
__global__ void k_outmlp(const float* __restrict__ hin,
                         const float* __restrict__ W1, const float* __restrict__ b1,
                         const float* __restrict__ W2, const float* __restrict__ b2,
                         const float* __restrict__ W3, const float* __restrict__ b3,
                         float* __restrict__ out) {
    __shared__ float sW1[64 * 64], sW2[64 * 32], sW3[32 * 8];
    __shared__ float sb1[64], sb2[32], sb3[8];
    __shared__ float sh[8][64], sh1[8][64], sh2[8][32];
    for (int i = threadIdx.x; i < 64 * 64; i += blockDim.x) sW1[i] = W1[i];
    for (int i = threadIdx.x; i < 64 * 32; i += blockDim.x) sW2[i] = W2[i];
    for (int i = threadIdx.x; i < 32 * 8; i += blockDim.x) sW3[i] = W3[i];
    for (int i = threadIdx.x; i < 64; i += blockDim.x) sb1[i] = b1[i];
    for (int i = threadIdx.x; i < 32; i += blockDim.x) sb2[i] = b2[i];
    for (int i = threadIdx.x; i < 8; i += blockDim.x) sb3[i] = b3[i];
    __syncthreads();
    int wib = threadIdx.x >> 5;
    int lane = threadIdx.x & 31;
    for (int nd = 0; nd < 8; nd++) {
        int d = blockIdx.x * 64 + wib * 8 + nd;
        if (d >= N_NODES) continue;
        sh[wib][lane] = hin[d * 64 + lane];
        sh[wib][lane + 32] = hin[d * 64 + lane + 32];
        __syncwarp();
        float a0 = sb1[lane], a1 = sb1[lane + 32];
#pragma unroll
        for (int i = 0; i < 64; i++) {
            float xv = sh[wib][i];
            a0 += xv * sW1[i * 64 + lane];
            a1 += xv * sW1[i * 64 + lane + 32];
        }
        sh1[wib][lane] = eluf(a0);
        sh1[wib][lane + 32] = eluf(a1);
        __syncwarp();
        float a = sb2[lane];
#pragma unroll
        for (int i = 0; i < 64; i++) a += sh1[wib][i] * sW2[i * 32 + lane];
        sh2[wib][lane] = eluf(a);
        __syncwarp();
        if (lane < 8) {
            float o = sb3[lane];
#pragma unroll
            for (int i = 0; i < 32; i++) o += sh2[wib][i] * sW3[i * 8 + lane];
            out[d * 8 + lane] = o;
        }
        __syncwarp();
    }
}

// ---------------- launch ----------------
extern "C" void kernel_launch(void* const* d_in, const int* in_sizes, int n_in,
                              void* d_out, int out_size) {
    const float* x      = (const float*)d_in[0];
    const void*  ei     = d_in[1];
    const float* W_enc1 = (const float*)d_in[2];
    const float* b_enc1 = (const float*)d_in[3];
    const float* W_enc2 = (const float*)d_in[4];
    const float* b_enc2 = (const float*)d_in[5];
    const float* W_g[3] = {(const float*)d_in[6],  (const float*)d_in[10], (const float*)d_in[14]};
    const float* as_[3] = {(const float*)d_in[7],  (const float*)d_in[11], (const float*)d_in[15]};
    const float* ad_[3] = {(const float*)d_in[8],  (const float*)d_in[12], (const float*)d_in[16]};
    const float* bg_[3] = {(const float*)d_in[9],  (const float*)d_in[13], (const float*)d_in[17]};
    const float* W_o1 = (const float*)d_in[18];
    const float* b_o1 = (const float*)d_in[19];
    const float* W_o2 = (const float*)d_in[20];
    const float* b_o2 = (const float*)d_in[21];
    const float* W_o3 = (const float*)d_in[22];
    const float* b_o3 = (const float*)d_in[23];
    float* out = (float*)d_out;

    static bool inited = false;
    static cudaStream_t sB;
    static cudaEvent_t evF, evJ;
    static float* hA_p = nullptr;
    static float* hB_p = nullptr;
    static __half* hp_p = nullptr;
    static float* asrc_p = nullptr;
    static float* adst_p = nullptr;
    static int* deg_p = nullptr;
    if (!inited) {
        cudaStreamCreateWithFlags(&sB, cudaStreamNonBlocking);
        cudaEventCreateWithFlags(&evF, cudaEventDisableTiming);
        cudaEventCreateWithFlags(&evJ, cudaEventDisableTiming);
        cudaGetSymbolAddress((void**)&hA_p, g_hA);
        cudaGetSymbolAddress((void**)&hB_p, g_hB);
        cudaGetSymbolAddress((void**)&hp_p, g_hproj);
        cudaGetSymbolAddress((void**)&asrc_p, g_asrc);
        cudaGetSymbolAddress((void**)&adst_p, g_adst);
        cudaGetSymbolAddress((void**)&deg_p, g_deg);
        inited = true;
    }
    cudaStream_t s0 = 0;

    // fork: side stream does layer-1 dense work while stream 0 builds CSR
    cudaEventRecord(evF, s0);
    cudaStreamWaitEvent(sB, evF, 0);

    // stream 0: CSR build
    k_detect<<<1, 256, 0, s0>>>((const int*)ei);
    cudaMemsetAsync(deg_p, 0, N_NODES * sizeof(int), s0);
    k_count<<<(N_EDGES + 255) / 256, 256, 0, s0>>>(ei);
    k_scan1<<<NB_SCAN, 256, 0, s0>>>();
    k_scan3<<<NB_SCAN, 256, 0, s0>>>();
    k_scatter<<<(TOT_EDGES + 255) / 256, 256, 0, s0>>>(ei);

    dim3 ggrid((N_NODES + 63) / 64, 2);

    // side stream: fused encoder + layer-1 projection + attention coeffs
    k_gemm_enc<<<ggrid, 256, 0, sB>>>(x, W_enc1, b_enc1, W_enc2, b_enc2,
                                      W_g[0], as_[0], ad_[0], hp_p, asrc_p, adst_p, hA_p);

    // join
    cudaEventRecord(evJ, sB);
    cudaStreamWaitEvent(s0, evJ, 0);

    // layer 1 aggregate, then layers 2-3 serial on stream 0
    k_agg<<<(N_NODES + 7) / 8, 256, 0, s0>>>(bg_[0], hA_p, hB_p, hp_p);

    k_gemm_att<<<ggrid, 256, 0, s0>>>(hB_p, W_g[1], as_[1], ad_[1], hp_p, asrc_p, adst_p);
    k_agg<<<(N_NODES + 7) / 8, 256, 0, s0>>>(bg_[1], hB_p, hA_p, hp_p);

    k_gemm_att<<<ggrid, 256, 0, s0>>>(hA_p, W_g[2], as_[2], ad_[2], hp_p, asrc_p, adst_p);
    k_agg<<<(N_NODES + 7) / 8, 256, 0, s0>>>(bg_[2], hA_p, hB_p, hp_p);

    k_outmlp<<<(N_NODES + 63) / 64, 256, 0, s0>>>(hB_p, W_o1, b_o1, W_o2, b_o2, W_o3, b_o3, out);

    (void)in_sizes; (void)n_in; (void)out_size;
}